// round 2
// baseline (speedup 1.0000x reference)
#include <cuda_runtime.h>
#include <cuda_bf16.h>
#include <cstdint>

// ============================================================================
// Problem constants
// ============================================================================
#define KDIM 4096
#define NDIM 4096
#define MDIM 4096        // B*S = 2*2048
#define NB   (NDIM / 32) // 128 N-block rows
#define KB   (KDIM / 32) // 128 K-blocks per row

#define STAGES 4
#define A_BYTES (128 * 32 * 4)   // 16384  A tile [128m x 32k]
#define W_BYTES (32 * 32 * 4)    // 4096   W tile [32n x 32k]
#define STAGE_BYTES (A_BYTES + W_BYTES)          // 20480
#define SMEM_KLIST 0                              // 512B
#define SMEM_BIAS  512                            // 128B
#define SMEM_STAGE 1024
#define SMEM_TOTAL (SMEM_STAGE + STAGES * STAGE_BYTES)  // 82944

// ============================================================================
// Device globals (no allocation allowed)
// ============================================================================
__device__ int g_bm[NB * KB];       // block-active bitmap
__device__ int g_klist[NB * KB];    // per-Nb compacted active kb list
__device__ int g_kcount[NB];        // per-Nb active count

// ============================================================================
// Helpers
// ============================================================================
__device__ __forceinline__ uint32_t smem_u32(const void* p) {
    uint32_t a;
    asm("{ .reg .u64 t; cvta.to.shared.u64 t, %1; cvt.u32.u64 %0, t; }"
        : "=r"(a) : "l"(p));
    return a;
}

__device__ __forceinline__ void cp_async16(uint32_t saddr, const void* gaddr) {
    asm volatile("cp.async.cg.shared.global [%0], [%1], 16;"
                 :: "r"(saddr), "l"(gaddr) : "memory");
}
#define CP_ASYNC_COMMIT() asm volatile("cp.async.commit_group;" ::: "memory")
#define CP_ASYNC_WAIT(n)  asm volatile("cp.async.wait_group %0;" :: "n"(n) : "memory")

// Load fp32 from shared, round-to-nearest into tf32 bit pattern.
__device__ __forceinline__ uint32_t lds_tf32(uint32_t addr) {
    float v;
    asm volatile("ld.shared.f32 %0, [%1];" : "=f"(v) : "r"(addr));
    uint32_t t;
    asm("cvt.rna.tf32.f32 %0, %1;" : "=r"(t) : "f"(v));
    return t;
}

// m16n8k8 tf32 mma: D += A * B^T (row.col)
__device__ __forceinline__ void mma_tf32(float* c, const uint32_t* a, const uint32_t* b) {
    asm volatile(
        "mma.sync.aligned.m16n8k8.row.col.f32.tf32.tf32.f32 "
        "{%0,%1,%2,%3}, {%4,%5,%6,%7}, {%8,%9}, {%0,%1,%2,%3};"
        : "+f"(c[0]), "+f"(c[1]), "+f"(c[2]), "+f"(c[3])
        : "r"(a[0]), "r"(a[1]), "r"(a[2]), "r"(a[3]), "r"(b[0]), "r"(b[1]));
}

// ============================================================================
// Kernel 1: pool mask 32x32 blocks -> g_bm.  One warp per block.
// ============================================================================
__global__ __launch_bounds__(256) void mask_pool_kernel(const int* __restrict__ mask) {
    int gw = blockIdx.x * 8 + (threadIdx.x >> 5);   // 0..16383
    int lane = threadIdx.x & 31;
    int nb = gw >> 7;
    int kb = gw & 127;
    size_t row_off = (size_t)(nb * 32 + lane) * KDIM + (size_t)kb * 32;

    const int4* mp = (const int4*)(mask + row_off);
    int acc = 0;
#pragma unroll
    for (int i = 0; i < 8; i++) {
        int4 v = mp[i];
        acc |= v.x | v.y | v.z | v.w;
    }
    unsigned any = __ballot_sync(0xffffffffu, acc != 0);
    if (lane == 0) g_bm[gw] = (any != 0u);
}

// ============================================================================
// Kernel 2: compact per-Nb active kb list (deterministic order).
// 4 CTAs x 32 warps; warp per nb row.
// ============================================================================
__global__ __launch_bounds__(1024) void compact_kernel() {
    int nb = blockIdx.x * 32 + (threadIdx.x >> 5);
    int lane = threadIdx.x & 31;
    int count = 0;
#pragma unroll
    for (int r = 0; r < 4; r++) {
        int kb = r * 32 + lane;
        int a = g_bm[nb * KB + kb];
        unsigned bal = __ballot_sync(0xffffffffu, a);
        int pos = count + __popc(bal & ((1u << lane) - 1u));
        if (a) g_klist[nb * KB + pos] = kb;
        count += __popc(bal);
    }
    if (lane == 0) g_kcount[nb] = count;
}

// ============================================================================
// Kernel 3: block-sparse tf32 GEMM.
// out[M,N] = data[M,K] @ weight[N,K]^T (active blocks only) + bias
// CTA: 128m x 32n (one Nb row), 4 warps (warp = 32m x 32n).
// grid.x = nb (128), grid.y = mtile (32).
// ============================================================================
__global__ __launch_bounds__(128, 2) void gemm_sparse_kernel(
    const float* __restrict__ A,      // [M, K]
    const float* __restrict__ W,      // [N, K]
    const float* __restrict__ bias,   // [N]
    float* __restrict__ out) {        // [M, N]
    extern __shared__ char smem[];
    const uint32_t sb = smem_u32(smem);
    const int tid = threadIdx.x;
    const int wid = tid >> 5;
    const int lane = tid & 31;
    const int nb = blockIdx.x;
    const int mtile = blockIdx.y;

    const int cnt = g_kcount[nb];
    if (tid < 128) ((int*)smem)[tid] = g_klist[nb * KB + tid];
    if (tid < 32)  ((float*)(smem + SMEM_BIAS))[tid] = bias[nb * 32 + tid];
    __syncthreads();
    const int* sk = (const int*)smem;

    const float* Abase = A + (size_t)(mtile * 128) * KDIM;
    const float* Wbase = W + (size_t)(nb * 32) * KDIM;

    // ---- stage loader: A 1024 + W 256 16B chunks over 128 threads ----
    auto load_stage = [&](int s, int kb) {
        const uint32_t aT = sb + SMEM_STAGE + s * STAGE_BYTES;
        const uint32_t wT = aT + A_BYTES;
        const float* ag = Abase + kb * 32;
        const float* wg = Wbase + kb * 32;
#pragma unroll
        for (int q = 0; q < 8; q++) {
            int c = tid + q * 128;
            int row = c >> 3, cc = c & 7;
            uint32_t so = (uint32_t)(row * 128 + ((cc ^ (row & 7)) << 4));
            cp_async16(aT + so, ag + (size_t)row * KDIM + cc * 4);
        }
#pragma unroll
        for (int q = 0; q < 2; q++) {
            int c = tid + q * 128;
            int row = c >> 3, cc = c & 7;
            uint32_t so = (uint32_t)(row * 128 + ((cc ^ (row & 7)) << 4));
            cp_async16(wT + so, wg + (size_t)row * KDIM + cc * 4);
        }
    };

    float c_[2][4][4] = {};   // [m16-tile][n8-tile][frag]

    // ---- prologue ----
#pragma unroll
    for (int s0 = 0; s0 < STAGES - 1; s0++) {
        if (s0 < cnt) load_stage(s0, sk[s0]);
        CP_ASYNC_COMMIT();
    }

    const int g = lane >> 2;      // group id (rows / n-cols)
    const int q = lane & 3;       // thread in group (k / out-cols)
    const int mb = wid * 32;

    int s = 0;
    for (int i = 0; i < cnt; i++) {
        CP_ASYNC_WAIT(STAGES - 2);
        __syncthreads();

        int jn = i + STAGES - 1;
        if (jn < cnt) load_stage((s + STAGES - 1) & (STAGES - 1), sk[jn]);
        CP_ASYNC_COMMIT();

        const uint32_t aT = sb + SMEM_STAGE + s * STAGE_BYTES;
        const uint32_t wT = aT + A_BYTES;

#pragma unroll
        for (int j = 0; j < 4; j++) {          // 4 k-steps of 8
            uint32_t a_[2][4];
            uint32_t b_[4][2];
#pragma unroll
            for (int mt = 0; mt < 2; mt++) {
                int R0 = mb + mt * 16 + g;
                int R1 = R0 + 8;
                uint32_t ba0 = aT + R0 * 128 + q * 4;
                uint32_t ba1 = aT + R1 * 128 + q * 4;
                a_[mt][0] = lds_tf32(ba0 + (((2 * j)     ^ (R0 & 7)) << 4));
                a_[mt][1] = lds_tf32(ba1 + (((2 * j)     ^ (R1 & 7)) << 4));
                a_[mt][2] = lds_tf32(ba0 + (((2 * j + 1) ^ (R0 & 7)) << 4));
                a_[mt][3] = lds_tf32(ba1 + (((2 * j + 1) ^ (R1 & 7)) << 4));
            }
#pragma unroll
            for (int nt = 0; nt < 4; nt++) {
                int n = nt * 8 + g;
                uint32_t bb = wT + n * 128 + q * 4;
                b_[nt][0] = lds_tf32(bb + (((2 * j)     ^ (n & 7)) << 4));
                b_[nt][1] = lds_tf32(bb + (((2 * j + 1) ^ (n & 7)) << 4));
            }
#pragma unroll
            for (int mt = 0; mt < 2; mt++)
#pragma unroll
                for (int nt = 0; nt < 4; nt++)
                    mma_tf32(c_[mt][nt], a_[mt], b_[nt]);
        }
        s = (s + 1) & (STAGES - 1);
    }

    // ---- epilogue: add bias, store float2 pairs ----
    const float* sbias = (const float*)(smem + SMEM_BIAS);
#pragma unroll
    for (int mt = 0; mt < 2; mt++) {
        int row0 = mtile * 128 + mb + mt * 16 + g;
#pragma unroll
        for (int nt = 0; nt < 4; nt++) {
            int coll = nt * 8 + 2 * q;
            float b0 = sbias[coll];
            float b1 = sbias[coll + 1];
            float2 v0 = make_float2(c_[mt][nt][0] + b0, c_[mt][nt][1] + b1);
            float2 v1 = make_float2(c_[mt][nt][2] + b0, c_[mt][nt][3] + b1);
            size_t col = (size_t)nb * 32 + coll;
            *(float2*)(out + (size_t)row0 * NDIM + col) = v0;
            *(float2*)(out + (size_t)(row0 + 8) * NDIM + col) = v1;
        }
    }
}

// ============================================================================
// Launch
// ============================================================================
extern "C" void kernel_launch(void* const* d_in, const int* in_sizes, int n_in,
                              void* d_out, int out_size) {
    const float* data   = (const float*)d_in[0];   // [B,S,K] -> [M,K]
    const int*   mask   = (const int*)d_in[1];     // [N,K]
    const float* weight = (const float*)d_in[2];   // [N,K]
    const float* bias   = (const float*)d_in[3];   // [N]
    float* out = (float*)d_out;                    // [M,N]

    mask_pool_kernel<<<2048, 256>>>(mask);
    compact_kernel<<<4, 1024>>>();

    cudaFuncSetAttribute(gemm_sparse_kernel,
                         cudaFuncAttributeMaxDynamicSharedMemorySize, SMEM_TOTAL);
    dim3 grid(NB, MDIM / 128);     // x = nb (A slice L2-shared per wave), y = mtile
    gemm_sparse_kernel<<<grid, 128, SMEM_TOTAL>>>(data, weight, bias, out);
}

// round 3
// speedup vs baseline: 1.8930x; 1.8930x over previous
#include <cuda_runtime.h>
#include <cuda_fp16.h>
#include <cstdint>

// ============================================================================
// Problem constants
// ============================================================================
#define KDIM 4096
#define NDIM 4096
#define MDIM 4096        // B*S = 2*2048
#define NB   128         // N / 32
#define KB   128         // K / 32

#define STAGES 4
#define A_BYTES (256 * 32 * 2)   // 16384  A tile [256m x 32k] fp16
#define W_BYTES (32 * 32 * 2)    // 2048   W tile [32n x 32k] fp16
#define STAGE_BYTES (A_BYTES + W_BYTES)           // 18432
#define SMEM_KLIST 0                               // 512B
#define SMEM_BIAS  512                             // 128B
#define SMEM_STAGE 1024
#define SMEM_TOTAL (SMEM_STAGE + STAGES * STAGE_BYTES)  // 74752 -> 3 CTAs/SM

// ============================================================================
// Device globals (no allocation allowed)
// ============================================================================
__device__ int g_bm[NB * KB];                    // block-active bitmap
__device__ int g_klist[NB * KB];                 // per-Nb compacted kb list
__device__ int g_kcount[NB];                     // per-Nb active count
__device__ __half g_dh[(size_t)MDIM * KDIM];     // data  fp16 (32MB)
__device__ __half g_wh[(size_t)NDIM * KDIM];     // weight fp16 (32MB, active blocks only)

// ============================================================================
// Helpers
// ============================================================================
__device__ __forceinline__ uint32_t smem_u32(const void* p) {
    uint32_t a;
    asm("{ .reg .u64 t; cvta.to.shared.u64 t, %1; cvt.u32.u64 %0, t; }"
        : "=r"(a) : "l"(p));
    return a;
}

#define SWZ(off) ((uint32_t)(off) ^ ((((uint32_t)(off)) >> 3) & 0x70))

__device__ __forceinline__ void cp_async16(uint32_t saddr, const void* gaddr) {
    asm volatile("cp.async.cg.shared.global [%0], [%1], 16;"
                 :: "r"(saddr), "l"(gaddr) : "memory");
}
#define CP_ASYNC_COMMIT() asm volatile("cp.async.commit_group;" ::: "memory")
#define CP_ASYNC_WAIT(n)  asm volatile("cp.async.wait_group %0;" :: "n"(n) : "memory")

__device__ __forceinline__ void ldsm_x4(uint32_t addr, uint32_t* r) {
    asm volatile("ldmatrix.sync.aligned.m8n8.x4.shared.b16 {%0,%1,%2,%3}, [%4];"
                 : "=r"(r[0]), "=r"(r[1]), "=r"(r[2]), "=r"(r[3]) : "r"(addr));
}

// m16n8k16 fp16 mma, fp32 accum: D += A * B^T (row.col)
__device__ __forceinline__ void mma_f16(float* c, const uint32_t* a, const uint32_t* b) {
    asm volatile(
        "mma.sync.aligned.m16n8k16.row.col.f32.f16.f16.f32 "
        "{%0,%1,%2,%3}, {%4,%5,%6,%7}, {%8,%9}, {%0,%1,%2,%3};"
        : "+f"(c[0]), "+f"(c[1]), "+f"(c[2]), "+f"(c[3])
        : "r"(a[0]), "r"(a[1]), "r"(a[2]), "r"(a[3]), "r"(b[0]), "r"(b[1]));
}

// ============================================================================
// Kernel 1: pool mask 32x32 blocks -> g_bm.  One warp per block.
// ============================================================================
__global__ __launch_bounds__(256) void mask_pool_kernel(const int* __restrict__ mask) {
    int gw = blockIdx.x * 8 + (threadIdx.x >> 5);   // 0..16383
    int lane = threadIdx.x & 31;
    int nb = gw >> 7;
    int kb = gw & 127;
    size_t row_off = (size_t)(nb * 32 + lane) * KDIM + (size_t)kb * 32;

    const int4* mp = (const int4*)(mask + row_off);
    int acc = 0;
#pragma unroll
    for (int i = 0; i < 8; i++) {
        int4 v = mp[i];
        acc |= v.x | v.y | v.z | v.w;
    }
    unsigned any = __ballot_sync(0xffffffffu, acc != 0);
    if (lane == 0) g_bm[gw] = (any != 0u);
}

// ============================================================================
// Kernel 2: compact per-Nb active kb list (deterministic order).
// ============================================================================
__global__ __launch_bounds__(1024) void compact_kernel() {
    int nb = blockIdx.x * 32 + (threadIdx.x >> 5);
    int lane = threadIdx.x & 31;
    int count = 0;
#pragma unroll
    for (int r = 0; r < 4; r++) {
        int kb = r * 32 + lane;
        int a = g_bm[nb * KB + kb];
        unsigned bal = __ballot_sync(0xffffffffu, a);
        int pos = count + __popc(bal & ((1u << lane) - 1u));
        if (a) g_klist[nb * KB + pos] = kb;
        count += __popc(bal);
    }
    if (lane == 0) g_kcount[nb] = count;
}

// ============================================================================
// Kernel 3: convert data fp32 -> fp16 (fully coalesced)
// ============================================================================
__global__ __launch_bounds__(256) void cvt_data_kernel(const float* __restrict__ in) {
    size_t base = ((size_t)blockIdx.x * 256 + threadIdx.x) * 16;
    const float4* s = (const float4*)(in + base);
    __half2 h[8];
#pragma unroll
    for (int i = 0; i < 4; i++) {
        float4 v = s[i];
        h[2 * i]     = __floats2half2_rn(v.x, v.y);
        h[2 * i + 1] = __floats2half2_rn(v.z, v.w);
    }
    uint4* d = (uint4*)(g_dh + base);
    d[0] = reinterpret_cast<uint4*>(h)[0];
    d[1] = reinterpret_cast<uint4*>(h)[1];
}

// ============================================================================
// Kernel 4: convert ACTIVE weight blocks fp32 -> fp16 (inactive never read)
// ============================================================================
__global__ __launch_bounds__(256) void cvt_w_kernel(const float* __restrict__ w) {
    int gw = blockIdx.x * 8 + (threadIdx.x >> 5);
    if (!g_bm[gw]) return;
    int lane = threadIdx.x & 31;
    int nb = gw >> 7, kb = gw & 127;
    size_t off = (size_t)(nb * 32 + lane) * KDIM + (size_t)kb * 32;
    const float4* s = (const float4*)(w + off);
    __half2 h[16];
#pragma unroll
    for (int i = 0; i < 8; i++) {
        float4 v = s[i];
        h[2 * i]     = __floats2half2_rn(v.x, v.y);
        h[2 * i + 1] = __floats2half2_rn(v.z, v.w);
    }
    uint4* d = (uint4*)(g_wh + off);
#pragma unroll
    for (int i = 0; i < 4; i++) d[i] = reinterpret_cast<uint4*>(h)[i];
}

// ============================================================================
// Kernel 5: block-sparse fp16 GEMM.
// out[M,N] = data[M,K] @ weight[N,K]^T (active blocks only) + bias
// CTA: 256m x 32n, 4 warps (warp = 64m x 32n). grid = (nb=128, mtile=16).
// ============================================================================
__global__ __launch_bounds__(128) void gemm_sparse_kernel(
    const float* __restrict__ bias,   // [N]
    float* __restrict__ out) {        // [M, N]
    extern __shared__ char smem[];
    const uint32_t sb = smem_u32(smem);
    const int tid = threadIdx.x;
    const int wid = tid >> 5;
    const int lane = tid & 31;
    const int nb = blockIdx.x;
    const int mtile = blockIdx.y;

    const int cnt = g_kcount[nb];
    if (tid < 128) ((int*)smem)[tid] = g_klist[nb * KB + tid];
    if (tid < 32)  ((float*)(smem + SMEM_BIAS))[tid] = bias[nb * 32 + tid];
    __syncthreads();
    const int* sk = (const int*)smem;

    const __half* Abase = g_dh + (size_t)(mtile * 256) * KDIM;
    const __half* Wbase = g_wh + (size_t)(nb * 32) * KDIM;

    // ---- stage loader: A 1024 + W 128 16B chunks over 128 threads ----
    auto load_stage = [&](int s, int kb) {
        const uint32_t aT = sb + SMEM_STAGE + s * STAGE_BYTES;
        const uint32_t wT = aT + A_BYTES;
        const __half* ag = Abase + kb * 32;
        const __half* wg = Wbase + kb * 32;
#pragma unroll
        for (int q = 0; q < 8; q++) {
            int c = tid + q * 128;       // 0..1023
            int row = c >> 2, cc = c & 3;
            cp_async16(aT + SWZ(row * 64 + cc * 16),
                       ag + (size_t)row * KDIM + cc * 8);
        }
        {
            int row = tid >> 2, cc = tid & 3;
            cp_async16(wT + SWZ(row * 64 + cc * 16),
                       wg + (size_t)row * KDIM + cc * 8);
        }
    };

    float c_[4][4][4] = {};   // [m16-tile][n8-tile][frag]

    // ---- prologue ----
#pragma unroll
    for (int s0 = 0; s0 < STAGES - 1; s0++) {
        if (s0 < cnt) load_stage(s0, sk[s0]);
        CP_ASYNC_COMMIT();
    }

    // ldmatrix source rows (per thread)
    const int a_r  = (lane & 7) + ((lane >> 3) & 1) * 8;   // row within m16 tile
    const int a_ch = lane >> 4;                            // +0/+1 k-chunk
    const int b_r  = ((lane >> 4) & 1) * 8 + (lane & 7);   // n row (nt pair)
    const int b_ch = (lane >> 3) & 1;                      // k-chunk

    int s = 0;
    for (int i = 0; i < cnt; i++) {
        CP_ASYNC_WAIT(STAGES - 2);
        __syncthreads();

        int jn = i + STAGES - 1;
        if (jn < cnt) load_stage((s + STAGES - 1) & (STAGES - 1), sk[jn]);
        CP_ASYNC_COMMIT();

        const uint32_t aT = sb + SMEM_STAGE + s * STAGE_BYTES;
        const uint32_t wT = aT + A_BYTES;

#pragma unroll
        for (int j = 0; j < 2; j++) {          // two k16 steps
            uint32_t af[4][4];
#pragma unroll
            for (int mt = 0; mt < 4; mt++) {
                int row = wid * 64 + mt * 16 + a_r;
                int ch = 2 * j + a_ch;
                ldsm_x4(aT + SWZ(row * 64 + ch * 16), af[mt]);
            }
            uint32_t bx[4], by[4];
            {
                int ch = 2 * j + b_ch;
                ldsm_x4(wT + SWZ(b_r * 64 + ch * 16), bx);          // nt0, nt1
                ldsm_x4(wT + SWZ((b_r + 16) * 64 + ch * 16), by);   // nt2, nt3
            }
            uint32_t bf[4][2] = {
                {bx[0], bx[1]}, {bx[2], bx[3]},
                {by[0], by[1]}, {by[2], by[3]}
            };
#pragma unroll
            for (int mt = 0; mt < 4; mt++)
#pragma unroll
                for (int nt = 0; nt < 4; nt++)
                    mma_f16(c_[mt][nt], af[mt], bf[nt]);
        }
        s = (s + 1) & (STAGES - 1);
    }

    // ---- epilogue: add bias, store float2 pairs ----
    const float* sbias = (const float*)(smem + SMEM_BIAS);
    const int g = lane >> 2;
    const int q = lane & 3;
#pragma unroll
    for (int mt = 0; mt < 4; mt++) {
        int row0 = mtile * 256 + wid * 64 + mt * 16 + g;
#pragma unroll
        for (int nt = 0; nt < 4; nt++) {
            int coll = nt * 8 + 2 * q;
            float b0 = sbias[coll];
            float b1 = sbias[coll + 1];
            float2 v0 = make_float2(c_[mt][nt][0] + b0, c_[mt][nt][1] + b1);
            float2 v1 = make_float2(c_[mt][nt][2] + b0, c_[mt][nt][3] + b1);
            size_t col = (size_t)nb * 32 + coll;
            *(float2*)(out + (size_t)row0 * NDIM + col) = v0;
            *(float2*)(out + (size_t)(row0 + 8) * NDIM + col) = v1;
        }
    }
}

// ============================================================================
// Launch
// ============================================================================
extern "C" void kernel_launch(void* const* d_in, const int* in_sizes, int n_in,
                              void* d_out, int out_size) {
    const float* data   = (const float*)d_in[0];   // [B,S,K] -> [M,K]
    const int*   mask   = (const int*)d_in[1];     // [N,K]
    const float* weight = (const float*)d_in[2];   // [N,K]
    const float* bias   = (const float*)d_in[3];   // [N]
    float* out = (float*)d_out;                    // [M,N]

    mask_pool_kernel<<<2048, 256>>>(mask);
    compact_kernel<<<4, 1024>>>();
    cvt_data_kernel<<<4096, 256>>>(data);
    cvt_w_kernel<<<2048, 256>>>(weight);

    cudaFuncSetAttribute(gemm_sparse_kernel,
                         cudaFuncAttributeMaxDynamicSharedMemorySize, SMEM_TOTAL);
    dim3 grid(NB, MDIM / 256);     // x = nb, y = mtile
    gemm_sparse_kernel<<<grid, 128, SMEM_TOTAL>>>(bias, out);
}